// round 1
// baseline (speedup 1.0000x reference)
#include <cuda_runtime.h>
#include <cstdint>

// Problem constants (tree fixed: 17 levels, perfect binary tree)
#define NN      131071          // total nodes
#define NSTEPS  335             // scan steps (T-1)
#define NSUB    256             // subtrees rooted at level 8
#define SUBN    511             // nodes per subtree (levels 0..8)
#define TOPN    255             // nodes in top tree (levels 9..16)
#define QLB     1e-4f
#define DTc     3600.0f

// Cross-block communication (static device memory — no allocation)
__device__ float g_root_raw[NSTEPS][NSUB];
__device__ int   g_ready[NSTEPS];

__global__ void init_kernel() {
    int i = blockIdx.x * blockDim.x + threadIdx.x;
    if (i < NSTEPS) g_ready[i] = 0;
}

struct NodeC {
    float A_coef, pexp, inv_ns, wet_c, tw, ssx2, len, a1, a2;
};

__device__ __forceinline__ NodeC make_node(int g,
    const float* __restrict__ nr,  const float* __restrict__ qsr,
    const float* __restrict__ len, const float* __restrict__ slope,
    const float* __restrict__ twp, const float* __restrict__ ssp,
    const float* __restrict__ xp)
{
    NodeC c;
    float n  = fmaf(nr[g], 0.34f, 0.01f);          // N_LO + raw*(N_HI-N_LO)
    float qs = 3.0f * qsr[g];                      // QS_LO + raw*(QS_HI-QS_LO)
    float s0 = fmaxf(slope[g], 1e-4f);
    float sq = sqrtf(s0);
    float den = fmaf(21.0f, sq, 1e-8f);            // P_SPATIAL*sqrt(s0) + 1e-8
    c.A_coef = n * (qs + 1.0f) / den;
    c.pexp   = 3.0f / fmaf(3.0f, qs, 5.0f);
    c.inv_ns = sq / n;
    float ssv = ssp[g];
    c.wet_c  = 2.0f * sqrtf(fmaf(ssv, ssv, 1.0f));
    c.tw     = twp[g];
    c.ssx2   = 2.0f * ssv;
    c.len    = len[g];
    float xv = xp[g];
    c.a1 = 2.0f * (1.0f - xv);
    c.a2 = 2.0f * xv;
    return c;
}

// Muskingum-Cunge per-node step: produces b (RHS) and c1 (parent coupling coef)
__device__ __forceinline__ void phase_a(const NodeC& c, float q, float it, float qpc,
                                        float& b, float& c1)
{
    float depth  = fmaxf(__powf(q * c.A_coef, c.pexp), 0.01f);
    float bottom = fmaxf(fmaf(-c.ssx2, depth, c.tw), 0.1f);
    float area   = (c.tw + bottom) * depth * 0.5f;
    float wetted = fmaf(depth, c.wet_c, bottom);
    float R      = __fdividef(area, wetted);
    float v      = c.inv_ns * __powf(R, 0.66666668f);
    v = fminf(fmaxf(v, 0.3f), 15.0f) * (5.0f / 3.0f);
    float k     = __fdividef(c.len, v);
    float denom = fmaf(k, c.a1, DTc);              // 2k(1-x)+DT
    float invd  = __fdividef(1.0f, denom);
    float ka2   = k * c.a2;                        // 2kx
    float c2 = (DTc + ka2) * invd;
    float c4 = (2.0f * DTc) * invd;
    c1 = (DTc - ka2) * invd;
    float c3 = 1.0f - c4;                          // (denom-2DT)/denom
    b = fmaf(c2, it, fmaf(c3, q, c4 * qpc));
}

__global__ void __launch_bounds__(256, 2)
route_kernel(const float* __restrict__ qp,
             const float* __restrict__ nr,  const float* __restrict__ qsr,
             const float* __restrict__ len, const float* __restrict__ slope,
             const float* __restrict__ twp, const float* __restrict__ ssp,
             const float* __restrict__ xp,  float* __restrict__ out)
{
    __shared__ float s_q [SUBN];   // carry state (worker) / qtop[0..254] (top)
    __shared__ float s_b [SUBN];   // b, then swept q1 (raw)
    __shared__ float s_c1[SUBN];
    __shared__ float s_cr[NSUB];   // top only: subtree-root child values

    const int tid = threadIdx.x;
    const int blk = blockIdx.x;

    if (blk < NSUB) {
        // ================= WORKER: owns subtree `s` (levels 0..8), never waits
        const int s = blk;
        // local heap (root-first): node i, children 2i+1, 2i+2
        // thread handles internal node i_int = tid (tid<255) and leaf i_leaf = 255+tid
        const int i_leaf  = 255 + tid;
        const int gid_leaf = s * 256 + tid;                 // level-0 global index
        const bool has_int = (tid < 255);
        int gid_int = 0;
        if (has_int) {
            int d = 31 - __clz(tid + 1);                    // depth from subtree root
            gid_int = 131072 - (1 << (9 + d)) + (s << d) + (tid + 1 - (1 << d));
        }
        NodeC cL = make_node(gid_leaf, nr, qsr, len, slope, twp, ssp, xp);
        NodeC cI;
        if (has_int) cI = make_node(gid_int, nr, qsr, len, slope, twp, ssp, xp);

        // carry init: q0 = q_prime[0] (raw, no clamp)
        s_q[i_leaf] = qp[gid_leaf];
        if (has_int) s_q[tid] = qp[gid_int];
        __syncthreads();

        for (int t = 0; t < NSTEPS; ++t) {
            const float* row = qp + (size_t)t * NN;
            // phase A
            float qL  = s_q[i_leaf];
            float bL, c1L;
            phase_a(cL, qL, 0.0f, fmaxf(row[gid_leaf], QLB), bL, c1L);
            float bI = 0.0f, c1I = 0.0f;
            if (has_int) {
                float qI = s_q[tid];
                float it = s_q[2 * tid + 1] + s_q[2 * tid + 2];
                phase_a(cI, qI, it, fmaxf(row[gid_int], QLB), bI, c1I);
            }
            s_b[i_leaf] = bL;
            if (has_int) { s_b[tid] = bI; s_c1[tid] = c1I; }
            __syncthreads();
            // sweep bottom-up: depths 7..0 (internal nodes only)
            #pragma unroll
            for (int dd = 7; dd >= 0; --dd) {
                int lo = (1 << dd) - 1, hi = (2 << dd) - 1;
                if (tid >= lo && tid < hi)
                    s_b[tid] = fmaf(s_c1[tid], s_b[2 * tid + 1] + s_b[2 * tid + 2], s_b[tid]);
                __syncthreads();
            }
            // publish subtree-root raw q1 + doorbell
            if (tid == 0) {
                g_root_raw[t][s] = s_b[0];
                __threadfence();
                atomicAdd(&g_ready[t], 1);
            }
            // carry update (clamped)
            s_q[i_leaf] = fmaxf(bL, QLB);               // leaf b unchanged by sweep
            if (has_int) s_q[tid] = fmaxf(s_b[tid], QLB);
            __syncthreads();
        }
    } else {
        // ================= TOP BLOCK: levels 9..16 (255 nodes, local heap)
        const bool hn = (tid < TOPN);
        int gid = 0;
        NodeC cT;
        if (hn) {
            int d = 31 - __clz(tid + 1);
            gid = 131072 - (1 << (1 + d)) + (tid + 1 - (1 << d));
            cT = make_node(gid, nr, qsr, len, slope, twp, ssp, xp);
            s_q[tid] = qp[gid];                        // q0 raw for top nodes
        }
        s_cr[tid] = qp[130560 + tid];                  // level-8 q0 raw (OFFS[8]=130560)
        if (tid == 0) out[0] = fmaxf(qp[NN - 1], QLB);
        __syncthreads();

        for (int t = 0; t < NSTEPS; ++t) {
            const float* row = qp + (size_t)t * NN;
            float b = 0.0f, c1 = 0.0f;
            if (hn) {
                float q = s_q[tid];
                float it;
                if (tid < 127) it = s_q[2 * tid + 1] + s_q[2 * tid + 2];
                else { int j = tid - 127; it = s_cr[2 * j] + s_cr[2 * j + 1]; }
                phase_a(cT, q, it, fmaxf(row[gid], QLB), b, c1);
            }
            __syncthreads();                           // reads of s_q/s_cr complete
            if (hn) { s_b[tid] = b; s_c1[tid] = c1; }
            // wait for all 256 subtree roots of step t
            if (tid == 0) {
                volatile int* rp = &g_ready[t];
                while (*rp < NSUB) { }
                __threadfence();
            }
            __syncthreads();
            float raw = __ldcg(&g_root_raw[t][tid]);   // L2 load (never in L1 before)
            s_cr[tid] = raw;                           // raw for sweep
            __syncthreads();
            // sweep leaves of top tree (depth 7: children = subtree roots, RAW q1)
            if (tid >= 127 && tid < 255) {
                int j = tid - 127;
                s_b[tid] = fmaf(s_c1[tid], s_cr[2 * j] + s_cr[2 * j + 1], s_b[tid]);
            }
            __syncthreads();
            #pragma unroll
            for (int dd = 6; dd >= 0; --dd) {
                int lo = (1 << dd) - 1, hi = (2 << dd) - 1;
                if (tid >= lo && tid < hi)
                    s_b[tid] = fmaf(s_c1[tid], s_b[2 * tid + 1] + s_b[2 * tid + 2], s_b[tid]);
                __syncthreads();
            }
            // state update (clamped carry), record output
            if (hn) s_q[tid] = fmaxf(s_b[tid], QLB);
            s_cr[tid] = fmaxf(s_cr[tid], QLB);         // clamped roots for next phase A
            if (tid == 0) out[t + 1] = fmaxf(s_b[0], QLB);
            __syncthreads();
        }
    }
}

extern "C" void kernel_launch(void* const* d_in, const int* in_sizes, int n_in,
                              void* d_out, int out_size)
{
    const float* qp    = (const float*)d_in[0];
    const float* nr    = (const float*)d_in[1];
    const float* qsr   = (const float*)d_in[2];
    const float* len   = (const float*)d_in[3];
    const float* slope = (const float*)d_in[4];
    const float* twp   = (const float*)d_in[5];
    const float* ssp   = (const float*)d_in[6];
    const float* xp    = (const float*)d_in[7];
    float* out = (float*)d_out;

    init_kernel<<<1, 384>>>();
    route_kernel<<<NSUB + 1, 256>>>(qp, nr, qsr, len, slope, twp, ssp, xp, out);
}

// round 3
// speedup vs baseline: 1.1810x; 1.1810x over previous
#include <cuda_runtime.h>
#include <cstdint>

#define NN      131071
#define NSTEPS  335
#define NSUB    256
#define SUBN    511
#define QLB     1e-4f
#define DTc     3600.0f

__device__ float g_root_raw[NSTEPS][NSUB];
__device__ int   g_ready[NSTEPS];

__global__ void init_kernel() {
    int i = blockIdx.x * blockDim.x + threadIdx.x;
    if (i < NSTEPS) g_ready[i] = 0;
}

struct NodeC {
    float A_coef, pexp, inv_ns, wet_c, tw, ssx2, a1len, a2len;
};

__device__ __forceinline__ NodeC make_node(int g,
    const float* __restrict__ nr,  const float* __restrict__ qsr,
    const float* __restrict__ len, const float* __restrict__ slope,
    const float* __restrict__ twp, const float* __restrict__ ssp,
    const float* __restrict__ xp)
{
    NodeC c;
    float n  = fmaf(nr[g], 0.34f, 0.01f);
    float qs = 3.0f * qsr[g];
    float s0 = fmaxf(slope[g], 1e-4f);
    float sq = sqrtf(s0);
    float den = fmaf(21.0f, sq, 1e-8f);
    c.A_coef = n * (qs + 1.0f) / den;
    c.pexp   = 3.0f / fmaf(3.0f, qs, 5.0f);
    c.inv_ns = sq / n;
    float ssv = ssp[g];
    c.wet_c  = 2.0f * sqrtf(fmaf(ssv, ssv, 1.0f));
    c.tw     = twp[g];
    c.ssx2   = 2.0f * ssv;
    float L  = len[g];
    float xv = xp[g];
    c.a1len = 2.0f * (1.0f - xv) * L;
    c.a2len = 2.0f * xv * L;
    return c;
}

// r = 1/(DT*v + a1len) = 1/(v*denom);  c1=(DTv-a2len)r; c2=(DTv+a2len)r; c4=2DTv*r; c3=1-c4
__device__ __forceinline__ void phase_a(const NodeC& c, float q, float it, float qpc,
                                        float& b, float& c1)
{
    float depth  = fmaxf(__powf(q * c.A_coef, c.pexp), 0.01f);
    float bottom = fmaxf(fmaf(-c.ssx2, depth, c.tw), 0.1f);
    float area   = (c.tw + bottom) * depth * 0.5f;
    float wetted = fmaf(depth, c.wet_c, bottom);
    float R      = __fdividef(area, wetted);
    float v      = c.inv_ns * __powf(R, 0.66666668f);
    v = fminf(fmaxf(v, 0.3f), 15.0f) * (5.0f / 3.0f);
    float dv = DTc * v;
    float r  = __fdividef(1.0f, dv + c.a1len);
    c1       = (dv - c.a2len) * r;
    float c2 = (dv + c.a2len) * r;
    float c4 = (2.0f * dv) * r;
    float c3 = 1.0f - c4;
    b = fmaf(c2, it, fmaf(c3, q, c4 * qpc));
}

__global__ void __launch_bounds__(512, 2)
route_kernel(const float* __restrict__ qp,
             const float* __restrict__ nr,  const float* __restrict__ qsr,
             const float* __restrict__ len, const float* __restrict__ slope,
             const float* __restrict__ twp, const float* __restrict__ ssp,
             const float* __restrict__ xp,  float* __restrict__ out)
{
    __shared__ float s_q [SUBN];
    __shared__ float s_b [SUBN];
    __shared__ float s_cr[NSUB];   // top only

    const int tid = threadIdx.x;
    const int blk = blockIdx.x;

    if (blk < NSUB) {
        // ===== WORKER: subtree s (tree levels 0..8), one node per thread, never waits
        const int s = blk;
        const bool is_leaf = (tid >= 256);
        const bool is_int  = (tid < 255);
        const bool active  = is_leaf || is_int;
        const int  hidx    = is_leaf ? (tid - 1) : tid;     // leaf heap = 255+(tid-256)
        int gid = 0, dd = -1;
        if (is_leaf) gid = s * 256 + (tid - 256);
        else if (is_int) {
            dd  = 31 - __clz(tid + 1);
            gid = 131072 - (1 << (9 + dd)) + (s << dd) + (tid + 1 - (1 << dd));
        }
        NodeC cN;
        if (active) cN = make_node(gid, nr, qsr, len, slope, twp, ssp, xp);

        if (active) s_q[hidx] = qp[gid];
        float qnext = active ? fmaxf(qp[gid], QLB) : 0.0f;   // row 0 for step 0
        __syncthreads();

        for (int t = 0; t < NSTEPS; ++t) {
            float qpc = qnext;
            int tn = (t + 1 < NSTEPS) ? t + 1 : t;
            if (active) qnext = fmaxf(__ldg(qp + (size_t)tn * NN + gid), QLB);
            float b = 0.0f, c1 = 0.0f;
            if (active) {
                float q  = s_q[hidx];
                float it = is_int ? (s_q[2 * tid + 1] + s_q[2 * tid + 2]) : 0.0f;
                phase_a(cN, q, it, qpc, b, c1);
                s_b[hidx] = b;
            }
            __syncthreads();
            if (is_leaf) s_q[hidx] = fmaxf(b, QLB);
            if (dd == 7) { b = fmaf(c1, s_b[2*tid+1] + s_b[2*tid+2], b); s_b[tid] = b; s_q[tid] = fmaxf(b, QLB); }
            __syncthreads();
            if (dd == 6) { b = fmaf(c1, s_b[2*tid+1] + s_b[2*tid+2], b); s_b[tid] = b; s_q[tid] = fmaxf(b, QLB); }
            __syncthreads();
            if (dd == 5) { b = fmaf(c1, s_b[2*tid+1] + s_b[2*tid+2], b); s_b[tid] = b; s_q[tid] = fmaxf(b, QLB); }
            __syncthreads();
            if (dd == 4) { b = fmaf(c1, s_b[2*tid+1] + s_b[2*tid+2], b); s_b[tid] = b; s_q[tid] = fmaxf(b, QLB); }
            __syncthreads();
            if (dd == 3) { b = fmaf(c1, s_b[2*tid+1] + s_b[2*tid+2], b); s_b[tid] = b; s_q[tid] = fmaxf(b, QLB); }
            __syncthreads();
            if (dd == 2) { b = fmaf(c1, s_b[2*tid+1] + s_b[2*tid+2], b); s_b[tid] = b; s_q[tid] = fmaxf(b, QLB); }
            __syncthreads();
            if (dd == 1) { b = fmaf(c1, s_b[2*tid+1] + s_b[2*tid+2], b); s_b[tid] = b; s_q[tid] = fmaxf(b, QLB); }
            __syncthreads();
            if (dd == 0) {
                b = fmaf(c1, s_b[1] + s_b[2], b);
                s_q[0] = fmaxf(b, QLB);
                g_root_raw[t][s] = b;        // raw root q1
                __threadfence();
                atomicAdd(&g_ready[t], 1);
            }
            __syncthreads();
        }
    } else {
        // ===== TOP: tree levels 9..16 (255 nodes). All 512 threads hit every barrier.
        const bool low = (tid < 256);
        const bool hn  = (tid < 255);
        int gid = 0, dd = -1;
        NodeC cT;
        if (hn) {
            dd  = 31 - __clz(tid + 1);
            gid = 131072 - (1 << (1 + dd)) + (tid + 1 - (1 << dd));
            cT  = make_node(gid, nr, qsr, len, slope, twp, ssp, xp);
            s_q[tid] = qp[gid];
        }
        if (low) s_cr[tid] = qp[130560 + tid];      // level-8 q0 (raw); OFFS[8]=130560
        if (tid == 0) out[0] = fmaxf(qp[NN - 1], QLB);
        float qnext = hn ? fmaxf(qp[gid], QLB) : 0.0f;
        __syncthreads();

        for (int t = 0; t < NSTEPS; ++t) {
            float qpc = qnext;
            int tn = (t + 1 < NSTEPS) ? t + 1 : t;
            if (hn) qnext = fmaxf(__ldg(qp + (size_t)tn * NN + gid), QLB);
            float b = 0.0f, c1 = 0.0f;
            if (hn) {
                float q = s_q[tid];
                float it;
                if (tid < 127) it = s_q[2 * tid + 1] + s_q[2 * tid + 2];
                else { int j = tid - 127; it = s_cr[2 * j] + s_cr[2 * j + 1]; }
                phase_a(cT, q, it, qpc, b, c1);
            }
            // wait for all 256 subtree roots of step t (round-1 doorbell, known good)
            if (tid == 0) {
                volatile int* rp = &g_ready[t];
                while (*rp < NSUB) { }
                __threadfence();
            }
            __syncthreads();                               // 1: phase-A smem reads done + roots visible
            if (low) s_cr[tid] = __ldcg(&g_root_raw[t][tid]);  // raw step-t roots
            if (hn)  s_b[tid] = b;
            __syncthreads();                               // 2
            if (dd == 7) { int j = tid - 127;
                b = fmaf(c1, s_cr[2*j] + s_cr[2*j+1], b); s_b[tid] = b; s_q[tid] = fmaxf(b, QLB); }
            __syncthreads();                               // 3
            if (dd == 6) { b = fmaf(c1, s_b[2*tid+1] + s_b[2*tid+2], b); s_b[tid] = b; s_q[tid] = fmaxf(b, QLB); }
            __syncthreads();                               // 4
            if (dd == 5) { b = fmaf(c1, s_b[2*tid+1] + s_b[2*tid+2], b); s_b[tid] = b; s_q[tid] = fmaxf(b, QLB); }
            __syncthreads();                               // 5
            if (dd == 4) { b = fmaf(c1, s_b[2*tid+1] + s_b[2*tid+2], b); s_b[tid] = b; s_q[tid] = fmaxf(b, QLB); }
            __syncthreads();                               // 6
            if (dd == 3) { b = fmaf(c1, s_b[2*tid+1] + s_b[2*tid+2], b); s_b[tid] = b; s_q[tid] = fmaxf(b, QLB); }
            __syncthreads();                               // 7
            if (dd == 2) { b = fmaf(c1, s_b[2*tid+1] + s_b[2*tid+2], b); s_b[tid] = b; s_q[tid] = fmaxf(b, QLB); }
            __syncthreads();                               // 8
            if (dd == 1) { b = fmaf(c1, s_b[2*tid+1] + s_b[2*tid+2], b); s_b[tid] = b; s_q[tid] = fmaxf(b, QLB); }
            __syncthreads();                               // 9
            if (dd == 0) {
                b = fmaf(c1, s_b[1] + s_b[2], b);
                float qr = fmaxf(b, QLB);
                s_q[0] = qr;
                out[t + 1] = qr;
            }
            if (low) s_cr[tid] = fmaxf(s_cr[tid], QLB);    // clamp roots for next phase A
            __syncthreads();                               // 10
        }
    }
}

extern "C" void kernel_launch(void* const* d_in, const int* in_sizes, int n_in,
                              void* d_out, int out_size)
{
    const float* qp    = (const float*)d_in[0];
    const float* nr    = (const float*)d_in[1];
    const float* qsr   = (const float*)d_in[2];
    const float* len   = (const float*)d_in[3];
    const float* slope = (const float*)d_in[4];
    const float* twp   = (const float*)d_in[5];
    const float* ssp   = (const float*)d_in[6];
    const float* xp    = (const float*)d_in[7];
    float* out = (float*)d_out;

    init_kernel<<<1, 384>>>();
    route_kernel<<<NSUB + 1, 512>>>(qp, nr, qsr, len, slope, twp, ssp, xp, out);
}

// round 5
// speedup vs baseline: 1.6777x; 1.4206x over previous
#include <cuda_runtime.h>
#include <cstdint>

#define NN      131071
#define NSTEPS  335
#define QLB     1e-4f
#define DTc     3600.0f
#define FULLM   0xFFFFFFFFu

// doorbells: flag(high 32) | float bits(low 32), one word per (step, node)
__device__ unsigned long long g1[NSTEPS * 4096];  // level-4 roots
__device__ unsigned long long g2[NSTEPS * 256];   // level-8 roots
__device__ unsigned long long g3[NSTEPS * 16];    // level-12 roots

__global__ void init_kernel() {
    int i = blockIdx.x * blockDim.x + threadIdx.x;
    if (i < NSTEPS * 4096) g1[i] = 0ull;
    if (i < NSTEPS * 256)  g2[i] = 0ull;
    if (i < NSTEPS * 16)   g3[i] = 0ull;
}

struct NodeC {
    float A_coef, pexp, inv_ns, wet_c, tw, ssx2, a1len, a2len;
};

__device__ __forceinline__ NodeC make_node(int g,
    const float* __restrict__ nr,  const float* __restrict__ qsr,
    const float* __restrict__ len, const float* __restrict__ slope,
    const float* __restrict__ twp, const float* __restrict__ ssp,
    const float* __restrict__ xp)
{
    NodeC c;
    float n  = fmaf(nr[g], 0.34f, 0.01f);
    float qs = 3.0f * qsr[g];
    float s0 = fmaxf(slope[g], 1e-4f);
    float sq = sqrtf(s0);
    float den = fmaf(21.0f, sq, 1e-8f);
    c.A_coef = n * (qs + 1.0f) / den;
    c.pexp   = 3.0f / fmaf(3.0f, qs, 5.0f);
    c.inv_ns = sq / n;
    float ssv = ssp[g];
    c.wet_c  = 2.0f * sqrtf(fmaf(ssv, ssv, 1.0f));
    c.tw     = twp[g];
    c.ssx2   = 2.0f * ssv;
    float L  = len[g];
    float xv = xp[g];
    c.a1len = 2.0f * (1.0f - xv) * L;
    c.a2len = 2.0f * xv * L;
    return c;
}

// r = 1/(DT*v + a1len);  c1=(DTv-a2len)r; c2=(DTv+a2len)r; c4=2DTv*r; c3=1-c4
__device__ __forceinline__ void phase_a(const NodeC& c, float q, float it, float qpc,
                                        float& b, float& c1)
{
    float depth  = fmaxf(__powf(q * c.A_coef, c.pexp), 0.01f);
    float bottom = fmaxf(fmaf(-c.ssx2, depth, c.tw), 0.1f);
    float area   = (c.tw + bottom) * depth * 0.5f;
    float wetted = fmaf(depth, c.wet_c, bottom);
    float R      = __fdividef(area, wetted);
    float v      = c.inv_ns * __powf(R, 0.66666668f);
    v = fminf(fmaxf(v, 0.3f), 15.0f) * (5.0f / 3.0f);
    float dv = DTc * v;
    float r  = __fdividef(1.0f, dv + c.a1len);
    c1       = (dv - c.a2len) * r;
    float c2 = (dv + c.a2len) * r;
    float c4 = (2.0f * dv) * r;
    float c3 = 1.0f - c4;
    b = fmaf(c2, it, fmaf(c3, q, c4 * qpc));
}

// Warp tiers: T1 levels 0-4 (4096 warps), T2 levels 5-8 (256), T3 levels 9-12 (16),
// T4 levels 13-16 (1). 15 internal nodes on lanes 0-14 (T1: +16 leaves on lanes
// 15-30); lanes 16-31 of T2..T4 poll the 16 child roots via acquire loads.
__global__ void __launch_bounds__(256, 4)
route_kernel(const float* __restrict__ qp,
             const float* __restrict__ nr,  const float* __restrict__ qsr,
             const float* __restrict__ len, const float* __restrict__ slope,
             const float* __restrict__ twp, const float* __restrict__ ssp,
             const float* __restrict__ xp,  float* __restrict__ out)
{
    const int w    = blockIdx.x * 8 + (threadIdx.x >> 5);
    const int lane = threadIdx.x & 31;
    if (w >= 4369) return;

    int tier, sub;
    if      (w >= 273) { tier = 1; sub = w - 273; }
    else if (w >= 17)  { tier = 2; sub = w - 17;  }
    else if (w >= 1)   { tier = 3; sub = w - 1;   }
    else               { tier = 4; sub = 0;       }

    bool is_node, is_poll = false;
    int  gid = 0, mydepth = 9;
    int  sA, sB;
    unsigned long long* pollp = 0; int pollstride = 0;
    unsigned long long* pubp  = 0; int pubstride  = 0;

    if (tier == 1) {
        is_node = (lane < 31);
        if (is_node) {
            int dh = 31 - __clz(lane + 1);            // depth below subtree root, 0..4
            mydepth = dh;                              // leaves have dh==4
            gid = 131072 - (1 << (13 + dh)) + (sub << dh) + (lane + 1 - (1 << dh));
        }
        sA = min(2 * lane + 1, 31); sB = min(2 * lane + 2, 31);
        pubp = g1 + sub; pubstride = 4096;
    } else {
        is_node = (lane < 15);
        is_poll = (lane >= 16);
        const int bs = (tier == 2) ? 9 : (tier == 3) ? 5 : 1;
        if (is_node) {
            int dh = 31 - __clz(lane + 1);            // 0..3
            mydepth = dh;
            gid = 131072 - (1 << (bs + dh)) + (sub << dh) + (lane + 1 - (1 << dh));
        }
        // depth-3 nodes (lanes 7..14): children live on poll lanes 16..31
        if (lane >= 7 && lane <= 14) { sA = 2 * lane + 2; sB = 2 * lane + 3; }
        else { sA = min(2 * lane + 1, 31); sB = min(2 * lane + 2, 31); }
        const int c = lane - 16;
        if (tier == 2)      { pollp = g1 + sub * 16 + c; pollstride = 4096; pubp = g2 + sub; pubstride = 256; }
        else if (tier == 3) { pollp = g2 + sub * 16 + c; pollstride = 256;  pubp = g3 + sub; pubstride = 16;  }
        else                { pollp = g3 + c;            pollstride = 16; }
    }

    NodeC cN;
    float cq = 0.0f, qnext = 0.0f;
    if (is_node) {
        cN = make_node(gid, nr, qsr, len, slope, twp, ssp, xp);
        cq = qp[gid];                                  // q0 raw (no clamp)
        qnext = fmaxf(cq, QLB);                        // qpc for step 0
    }
    if (is_poll) {
        const int bs2 = (tier == 2) ? 13 : (tier == 3) ? 9 : 5;
        int cgid = 131072 - (1 << bs2) + sub * 16 + (lane - 16);
        cq = qp[cgid];                                 // child q0 raw
    }
    if (tier == 4 && lane == 0) out[0] = fmaxf(qp[NN - 1], QLB);

    for (int t = 0; t < NSTEPS; ++t) {
        float qpc = qnext;
        if (is_node) {                                 // prefetch next step's q_prime
            int tn = (t + 1 < NSTEPS) ? t + 1 : t;
            qnext = fmaxf(__ldg(qp + (size_t)tn * NN + gid), QLB);
        }
        // i_t from children's carry registers (previous-step q)
        float itA = __shfl_sync(FULLM, cq, sA);
        float itB = __shfl_sync(FULLM, cq, sB);
        float b = 0.0f, c1 = 0.0f;
        if (is_node) {
            float it = (mydepth == 4) ? 0.0f : (itA + itB);  // T1 leaves: no inflow
            phase_a(cN, cq, it, qpc, b, c1);
        }
        if (is_poll) {                                 // fetch this step's child root (raw)
            unsigned long long v;
            do {
                asm volatile("ld.acquire.gpu.global.b64 %0, [%1];"
                             : "=l"(v) : "l"(pollp) : "memory");
            } while ((v >> 32) == 0ull);
            b = __uint_as_float((unsigned)v);
            pollp += pollstride;
        }
        __syncwarp(FULLM);
        // bottom-up sweep on raw values, 4 levels, pure shuffles
        #pragma unroll
        for (int d = 3; d >= 0; --d) {
            float bl = __shfl_sync(FULLM, b, sA);
            float br = __shfl_sync(FULLM, b, sB);
            if (mydepth == d) b = fmaf(c1, bl + br, b);
        }
        if (lane == 0) {
            if (tier == 4) out[t + 1] = fmaxf(b, QLB);
            else {
                unsigned long long pv = (1ull << 32) | (unsigned long long)__float_as_uint(b);
                asm volatile("st.release.gpu.global.b64 [%0], %1;"
                             :: "l"(pubp), "l"(pv) : "memory");
                pubp += pubstride;
            }
        }
        cq = fmaxf(b, QLB);                            // carry (nodes) / child carry (pollers)
    }
}

extern "C" void kernel_launch(void* const* d_in, const int* in_sizes, int n_in,
                              void* d_out, int out_size)
{
    const float* qp    = (const float*)d_in[0];
    const float* nr    = (const float*)d_in[1];
    const float* qsr   = (const float*)d_in[2];
    const float* len   = (const float*)d_in[3];
    const float* slope = (const float*)d_in[4];
    const float* twp   = (const float*)d_in[5];
    const float* ssp   = (const float*)d_in[6];
    const float* xp    = (const float*)d_in[7];
    float* out = (float*)d_out;

    init_kernel<<<(NSTEPS * 4096 + 255) / 256, 256>>>();
    route_kernel<<<547, 256>>>(qp, nr, qsr, len, slope, twp, ssp, xp, out);
}